// round 7
// baseline (speedup 1.0000x reference)
#include <cuda_runtime.h>

// ---------------------------------------------------------------------------
// EquivariantAttention — fp32 persistent kernel, 1 block/SM, all weights in smem
// Phase-3 (the 89%-of-FLOPs radial layer2) uses packed fma.rn.f32x2 with a
// duplicated-h operand layout so no pack instructions are needed.
// ---------------------------------------------------------------------------

namespace {

constexpr int NODES = 20000;
constexpr int NBR   = 16;
constexpr int MULT  = 8;
constexpr int DIMV  = 4;
constexpr int EDIM  = 32;
constexpr int HIDN  = 64;
constexpr int FLAT  = 256;   // (NL*MULT)^2
constexpr float ATT_SCALE = 0.35355339059327373f;   // 8^-0.5

struct alignas(16) SmemT {
    // weights (loaded once per block)
    float w2s[2][HIDN * FLAT];    // natural row-major: [br][c*256 + p]
    float w1s[2][EDIM * HIDN];    // [br][i*64 + c]
    float b1s[2][HIDN];
    float b2s[2][FLAT];
    float qw[16 * 8];
    float ow[16 * 8];
    float qb[8];
    float ob[8];
    int   idx[16];
    int   flag;
    int   _pad[3];
    // per-node working set
    float ef[16][32];
    float fsrc[16][32];
    float fnode[32];
    float bas1[2][16][8];         // [br][e][d*2+l]
    float bas2[2][16][8];         // [br][e][l*4+d]
    float hbuf2[2][16][2 * HIDN]; // [br][e][2c+{0,1}] = h duplicated pairs
    float tmpb[2][16][16];        // [br][e][m*2+l]
    float t2b[2][16][16];         // [br][e][i]  (i = m*2+l)
    float kvb[2][16][32];         // [br][e][m*4+d]
    float qvec[32];
    float attn[4][16];
    float ao[32];
};

__device__ __forceinline__ unsigned long long ffma2(
    unsigned long long a, unsigned long long b, unsigned long long c) {
    unsigned long long d;
    asm("fma.rn.f32x2 %0, %1, %2, %3;" : "=l"(d) : "l"(a), "l"(b), "l"(c));
    return d;
}
__device__ __forceinline__ unsigned long long fmul2(
    unsigned long long a, unsigned long long b) {
    unsigned long long d;
    asm("mul.rn.f32x2 %0, %1, %2;" : "=l"(d) : "l"(a), "l"(b));
    return d;
}

} // namespace

__global__ __launch_bounds__(512, 1)
void eqattn_kernel(
    const float* __restrict__ bk1, const float* __restrict__ bk2,
    const float* __restrict__ bv1, const float* __restrict__ bv2,
    const float* __restrict__ efeat, const float* __restrict__ fin,
    const float* __restrict__ q_w,  const float* __restrict__ q_b,
    const float* __restrict__ k_w1, const float* __restrict__ k_b1,
    const float* __restrict__ k_w2, const float* __restrict__ k_b2,
    const float* __restrict__ v_w1, const float* __restrict__ v_b1,
    const float* __restrict__ v_w2, const float* __restrict__ v_b2,
    const float* __restrict__ o_w,  const float* __restrict__ o_b,
    const int*   __restrict__ nidx32,
    float* __restrict__ out)
{
    extern __shared__ unsigned char smem_raw[];
    SmemT& S = *reinterpret_cast<SmemT*>(smem_raw);
    const int tid = threadIdx.x;

    // ---------------- prologue: stage all weights into smem ----------------
    {
        const float4* gk = reinterpret_cast<const float4*>(k_w2);
        const float4* gv = reinterpret_cast<const float4*>(v_w2);
        float4* s0 = reinterpret_cast<float4*>(S.w2s[0]);
        float4* s1 = reinterpret_cast<float4*>(S.w2s[1]);
        for (int t = tid; t < (HIDN * FLAT) / 4; t += 512) {
            s0[t] = gk[t];
            s1[t] = gv[t];
        }
    }
    {
        const float4* gk = reinterpret_cast<const float4*>(k_w1);
        const float4* gv = reinterpret_cast<const float4*>(v_w1);
        float4* s0 = reinterpret_cast<float4*>(S.w1s[0]);
        float4* s1 = reinterpret_cast<float4*>(S.w1s[1]);
        if (tid < (EDIM * HIDN) / 4) {
            s0[tid] = gk[tid];
            s1[tid] = gv[tid];
        }
    }
    {
        int br = tid >> 8, p = tid & 255;
        S.b2s[br][p] = (br ? v_b2 : k_b2)[p];
    }
    if (tid < 128) {
        int br = tid >> 6;
        S.b1s[br][tid & 63] = (br ? v_b1 : k_b1)[tid & 63];
        S.qw[tid] = q_w[tid];
        S.ow[tid] = o_w[tid];
    }
    if (tid < 8) { S.qb[tid] = q_b[tid]; S.ob[tid] = o_b[tid]; }
    if (tid == 0) {
        // sniff int64 vs int32 neighbor_idx: int64 little-endian high words are 0
        S.flag = (nidx32[1] == 0 && nidx32[3] == 0 &&
                  nidx32[5] == 0 && nidx32[7] == 0) ? 1 : 0;
    }
    __syncthreads();
    const bool is64 = (S.flag != 0);

    // layer2 thread geometry: warp = (branch, ehalf, pslice)
    //   warp tile = 8 edges x 64 p, full c=64 reduction.
    //   lane owns the p-pair p = psl*64 + 2*lane + {0,1}.
    const int warp  = tid >> 5;
    const int lane  = tid & 31;
    const int brw   = warp >> 3;           // 0=k, 1=v
    const int w7    = warp & 7;
    const int ehalf = w7 >> 2;             // edges ehalf*8 .. +7
    const int psl   = w7 & 3;              // p0 = psl*64
    const int e0l2  = ehalf << 3;
    const int p0    = psl << 6;
    const int j0    = (lane << 1) & 15;    // j index of even p
    const int irow  = (psl << 2) + (lane >> 3);   // i in 0..15

    // ---------------------------- node loop --------------------------------
    for (int n = blockIdx.x; n < NODES; n += gridDim.x) {

        // phase 0: neighbor indices
        if (tid < NBR) {
            long long base = (long long)n * NBR + tid;
            int v;
            if (is64) v = (int)(reinterpret_cast<const long long*>(nidx32)[base]);
            else      v = nidx32[base];
            S.idx[tid] = v;
        }
        __syncthreads();

        // phase 1: load edge feats, gathered source features, bases, f[n]
        {
            int e = tid >> 5, i = tid & 31;
            S.ef[e][i]   = efeat[(long long)n * (NBR * EDIM) + tid];
            S.fsrc[e][i] = fin[S.idx[e] * (MULT * DIMV) + i];
        }
        {
            int arr = tid >> 7;              // 0..3
            int e   = (tid >> 3) & 15;
            int x   = tid & 7;
            const float* src = (arr == 0) ? bk1 : (arr == 1) ? bk2 : (arr == 2) ? bv1 : bv2;
            float val = src[(long long)n * (NBR * 8) + e * 8 + x];
            if (arr == 0)      S.bas1[0][e][x] = val;
            else if (arr == 1) S.bas2[0][e][x] = val;
            else if (arr == 2) S.bas1[1][e][x] = val;
            else               S.bas2[1][e][x] = val;
        }
        if (tid < 32) S.fnode[tid] = fin[n * (MULT * DIMV) + tid];
        __syncthreads();

        // phase 2: layer1 (h = gelu(ef@w1+b1)) stored as (h,h) pairs; tmp; q
        {
            const int br  = tid >> 8;
            const int rem = tid & 255;
            const int c   = rem & 63;
            const int eg  = rem >> 6;        // 0..3, edges eg+4k
            float acc0, acc1, acc2, acc3;
            acc0 = acc1 = acc2 = acc3 = S.b1s[br][c];
            #pragma unroll
            for (int i4 = 0; i4 < EDIM; i4 += 4) {
                float wa = S.w1s[br][(i4 + 0) * HIDN + c];
                float wbv = S.w1s[br][(i4 + 1) * HIDN + c];
                float wc = S.w1s[br][(i4 + 2) * HIDN + c];
                float wd = S.w1s[br][(i4 + 3) * HIDN + c];
                float4 e0 = *reinterpret_cast<const float4*>(&S.ef[eg +  0][i4]);
                float4 e1 = *reinterpret_cast<const float4*>(&S.ef[eg +  4][i4]);
                float4 e2 = *reinterpret_cast<const float4*>(&S.ef[eg +  8][i4]);
                float4 e3 = *reinterpret_cast<const float4*>(&S.ef[eg + 12][i4]);
                acc0 = fmaf(e0.x, wa, acc0); acc0 = fmaf(e0.y, wbv, acc0);
                acc0 = fmaf(e0.z, wc, acc0); acc0 = fmaf(e0.w, wd, acc0);
                acc1 = fmaf(e1.x, wa, acc1); acc1 = fmaf(e1.y, wbv, acc1);
                acc1 = fmaf(e1.z, wc, acc1); acc1 = fmaf(e1.w, wd, acc1);
                acc2 = fmaf(e2.x, wa, acc2); acc2 = fmaf(e2.y, wbv, acc2);
                acc2 = fmaf(e2.z, wc, acc2); acc2 = fmaf(e2.w, wd, acc2);
                acc3 = fmaf(e3.x, wa, acc3); acc3 = fmaf(e3.y, wbv, acc3);
                acc3 = fmaf(e3.z, wc, acc3); acc3 = fmaf(e3.w, wd, acc3);
            }
            // exact gelu: x * Phi(x); store duplicated pairs for packed layer2
            float g0 = acc0 * normcdff(acc0);
            float g1 = acc1 * normcdff(acc1);
            float g2 = acc2 * normcdff(acc2);
            float g3 = acc3 * normcdff(acc3);
            *reinterpret_cast<float2*>(&S.hbuf2[br][eg +  0][2 * c]) = make_float2(g0, g0);
            *reinterpret_cast<float2*>(&S.hbuf2[br][eg +  4][2 * c]) = make_float2(g1, g1);
            *reinterpret_cast<float2*>(&S.hbuf2[br][eg +  8][2 * c]) = make_float2(g2, g2);
            *reinterpret_cast<float2*>(&S.hbuf2[br][eg + 12][2 * c]) = make_float2(g3, g3);
        }
        {
            const int br = tid >> 8;
            const int rem = tid & 255;
            const int e = rem >> 4;
            const int j = rem & 15;          // m*2 + l
            const int m = j >> 1, l = j & 1;
            const float* fr = S.fsrc[e];
            const float* b  = S.bas1[br][e];
            float t = fr[m * 4 + 0] * b[0 * 2 + l];
            t = fmaf(fr[m * 4 + 1], b[1 * 2 + l], t);
            t = fmaf(fr[m * 4 + 2], b[2 * 2 + l], t);
            t = fmaf(fr[m * 4 + 3], b[3 * 2 + l], t);
            S.tmpb[br][e][j] = t;
        }
        if (tid < 32) {
            const int m = tid >> 2, d = tid & 3;
            const int l = (d == 0) ? 0 : 1;
            float a = (d == 0) ? S.qb[m] : 0.0f;
            #pragma unroll
            for (int mp = 0; mp < MULT; mp++)
                a = fmaf(S.qw[(l * MULT + m) * MULT + mp], S.fnode[mp * 4 + d], a);
            S.qvec[tid] = a;
        }
        __syncthreads();

        // phase 3: layer2 — rw = h@w2 + b2 with packed f32x2, then t2 = rw@tmp
        {
            // accumulators: 8 edges, each a packed (p_even, p_odd) pair
            unsigned long long acc[8];
            {
                unsigned long long binit =
                    *reinterpret_cast<const unsigned long long*>(
                        &S.b2s[brw][p0 + 2 * lane]);
                #pragma unroll
                for (int e = 0; e < 8; e++) acc[e] = binit;
            }
            const float* w2b = &S.w2s[brw][p0 + 2 * lane];
            const float* h0 = S.hbuf2[brw][e0l2 + 0];
            const float* h1 = S.hbuf2[brw][e0l2 + 1];
            const float* h2 = S.hbuf2[brw][e0l2 + 2];
            const float* h3 = S.hbuf2[brw][e0l2 + 3];
            const float* h4 = S.hbuf2[brw][e0l2 + 4];
            const float* h5 = S.hbuf2[brw][e0l2 + 5];
            const float* h6 = S.hbuf2[brw][e0l2 + 6];
            const float* h7 = S.hbuf2[brw][e0l2 + 7];
            #pragma unroll 4
            for (int c2 = 0; c2 < 32; c2++) {
                const int fo = 4 * c2;   // float offset into hbuf2 rows (= 2c)
                // .x = (h[c],h[c]) , .y = (h[c+1],h[c+1])
                ulonglong2 hv0 = *reinterpret_cast<const ulonglong2*>(&h0[fo]);
                ulonglong2 hv1 = *reinterpret_cast<const ulonglong2*>(&h1[fo]);
                ulonglong2 hv2 = *reinterpret_cast<const ulonglong2*>(&h2[fo]);
                ulonglong2 hv3 = *reinterpret_cast<const ulonglong2*>(&h3[fo]);
                ulonglong2 hv4 = *reinterpret_cast<const ulonglong2*>(&h4[fo]);
                ulonglong2 hv5 = *reinterpret_cast<const ulonglong2*>(&h5[fo]);
                ulonglong2 hv6 = *reinterpret_cast<const ulonglong2*>(&h6[fo]);
                ulonglong2 hv7 = *reinterpret_cast<const ulonglong2*>(&h7[fo]);
                unsigned long long w0 = *reinterpret_cast<const unsigned long long*>(
                    &w2b[(2 * c2) * FLAT]);
                unsigned long long w1 = *reinterpret_cast<const unsigned long long*>(
                    &w2b[(2 * c2 + 1) * FLAT]);
                acc[0] = ffma2(hv0.x, w0, acc[0]); acc[0] = ffma2(hv0.y, w1, acc[0]);
                acc[1] = ffma2(hv1.x, w0, acc[1]); acc[1] = ffma2(hv1.y, w1, acc[1]);
                acc[2] = ffma2(hv2.x, w0, acc[2]); acc[2] = ffma2(hv2.y, w1, acc[2]);
                acc[3] = ffma2(hv3.x, w0, acc[3]); acc[3] = ffma2(hv3.y, w1, acc[3]);
                acc[4] = ffma2(hv4.x, w0, acc[4]); acc[4] = ffma2(hv4.y, w1, acc[4]);
                acc[5] = ffma2(hv5.x, w0, acc[5]); acc[5] = ffma2(hv5.y, w1, acc[5]);
                acc[6] = ffma2(hv6.x, w0, acc[6]); acc[6] = ffma2(hv6.y, w1, acc[6]);
                acc[7] = ffma2(hv7.x, w0, acc[7]); acc[7] = ffma2(hv7.y, w1, acc[7]);
            }
            // t2 tail: contrib = rw_even*tmp[j0] + rw_odd*tmp[j0+1], fold 8 lanes
            #pragma unroll
            for (int e = 0; e < 8; e++) {
                unsigned long long tp =
                    *reinterpret_cast<const unsigned long long*>(
                        &S.tmpb[brw][e0l2 + e][j0]);
                unsigned long long pr = fmul2(acc[e], tp);
                float2 p2 = *reinterpret_cast<float2*>(&pr);
                float s = p2.x + p2.y;
                s += __shfl_xor_sync(0xffffffffu, s, 1);
                s += __shfl_xor_sync(0xffffffffu, s, 2);
                s += __shfl_xor_sync(0xffffffffu, s, 4);
                if ((lane & 7) == 0) S.t2b[brw][e0l2 + e][irow] = s;
            }
        }
        __syncthreads();

        // phase 4: k/v = t2 x bas2   (1024 items, 2/thread)
        #pragma unroll
        for (int rep = 0; rep < 2; rep++) {
            int it = tid + rep * 512;
            int br = it >> 9;
            int rem = it & 511;
            int e = rem >> 5;
            int p = rem & 31;                // o*4 + d
            int o = p >> 2, d = p & 3;
            float v = S.t2b[br][e][o * 2 + 0] * S.bas2[br][e][0 * 4 + d];
            v = fmaf(S.t2b[br][e][o * 2 + 1], S.bas2[br][e][1 * 4 + d], v);
            S.kvb[br][e][p] = v;
        }
        __syncthreads();

        // phase 5: logits + softmax (64 threads = warps 0,1; 16-lane groups)
        if (tid < 64) {
            const int h = tid >> 4, kk = tid & 15;
            float acc = 0.0f;
            #pragma unroll
            for (int dd = 0; dd < 8; dd++)
                acc = fmaf(S.qvec[h * 8 + dd], S.kvb[0][kk][h * 8 + dd], acc);
            acc *= ATT_SCALE;
            float mx = acc;
            #pragma unroll
            for (int o = 8; o >= 1; o >>= 1)
                mx = fmaxf(mx, __shfl_xor_sync(0xffffffffu, mx, o));
            float ex = expf(acc - mx);
            float sm = ex;
            #pragma unroll
            for (int o = 8; o >= 1; o >>= 1)
                sm += __shfl_xor_sync(0xffffffffu, sm, o);
            S.attn[h][kk] = ex / sm;
        }
        __syncthreads();

        // phase 6: attention output (32 threads)
        if (tid < 32) {
            const int h = tid >> 3;
            float acc = 0.0f;
            #pragma unroll
            for (int kk = 0; kk < NBR; kk++)
                acc = fmaf(S.attn[h][kk], S.kvb[1][kk][tid], acc);
            S.ao[tid] = acc;
        }
        __syncthreads();

        // phase 7: final eq_linear -> global
        if (tid < 32) {
            const int m = tid >> 2, d = tid & 3;
            const int l = (d == 0) ? 0 : 1;
            float a = (d == 0) ? S.ob[m] : 0.0f;
            #pragma unroll
            for (int mp = 0; mp < MULT; mp++)
                a = fmaf(S.ow[(l * MULT + m) * MULT + mp], S.ao[mp * 4 + d], a);
            out[(long long)n * 32 + tid] = a;
        }
        __syncthreads();
    }
}

extern "C" void kernel_launch(void* const* d_in, const int* in_sizes, int n_in,
                              void* d_out, int out_size) {
    const float* bk1  = (const float*)d_in[0];
    const float* bk2  = (const float*)d_in[1];
    const float* bv1  = (const float*)d_in[2];
    const float* bv2  = (const float*)d_in[3];
    const float* ef   = (const float*)d_in[4];
    const float* fin  = (const float*)d_in[5];
    const float* q_w  = (const float*)d_in[6];
    const float* q_b  = (const float*)d_in[7];
    const float* k_w1 = (const float*)d_in[8];
    const float* k_b1 = (const float*)d_in[9];
    const float* k_w2 = (const float*)d_in[10];
    const float* k_b2 = (const float*)d_in[11];
    const float* v_w1 = (const float*)d_in[12];
    const float* v_b1 = (const float*)d_in[13];
    const float* v_w2 = (const float*)d_in[14];
    const float* v_b2 = (const float*)d_in[15];
    const float* o_w  = (const float*)d_in[16];
    const float* o_b  = (const float*)d_in[17];
    const int*   nidx = (const int*)d_in[18];
    float* out = (float*)d_out;

    int sms = 148;
    cudaDeviceGetAttribute(&sms, cudaDevAttrMultiProcessorCount, 0);
    if (sms <= 0) sms = 148;

    const int smem = (int)sizeof(SmemT);
    cudaFuncSetAttribute(eqattn_kernel,
                         cudaFuncAttributeMaxDynamicSharedMemorySize, smem);

    eqattn_kernel<<<sms, 512, smem>>>(
        bk1, bk2, bv1, bv2, ef, fin,
        q_w, q_b, k_w1, k_b1, k_w2, k_b2,
        v_w1, v_b1, v_w2, v_b2, o_w, o_b,
        nidx, out);
}

// round 8
// speedup vs baseline: 2.2878x; 2.2878x over previous
#include <cuda_runtime.h>

// ---------------------------------------------------------------------------
// EquivariantAttention — fp32 persistent kernel, 1 block/SM, all weights in smem.
// Software-pipelined node loop: node n+1's global loads (idx -> gather chain,
// edge feats, bases, f) are issued at the top of iteration n and stored into a
// double-buffered smem region before the iteration's last barrier.
// ---------------------------------------------------------------------------

namespace {

constexpr int NODES = 20000;
constexpr int NBR   = 16;
constexpr int MULT  = 8;
constexpr int DIMV  = 4;
constexpr int EDIM  = 32;
constexpr int HIDN  = 64;
constexpr int FLAT  = 256;   // (NL*MULT)^2
constexpr float ATT_SCALE = 0.35355339059327373f;   // 8^-0.5

struct alignas(16) SmemT {
    // weights (loaded once per block)
    float w2s[2][HIDN * FLAT];   // repacked swizzled layout (see pos calc)
    float w1s[2][EDIM * HIDN];   // [br][i*64 + c]
    float b1s[2][HIDN];
    float b2s[2][FLAT];
    float qw[16 * 8];
    float ow[16 * 8];
    float qb[8];
    float ob[8];
    // per-node input set (double-buffered for the prefetch pipeline)
    float ef[2][16][32];
    float fsrc[2][16][32];
    float fnode[2][32];
    float bas1[2][2][16][8];     // [buf][br][e][d*2+l]
    float bas2[2][2][16][8];     // [buf][br][e][l*4+d]
    // per-node intermediates (single-buffered; produced+consumed between syncs)
    float hbuf[2][16][HIDN];
    float tmpb[2][16][16];       // [br][e][m*2+l]
    float t2b[2][16][16];        // [br][e][o*2+l]
    float kvb[2][16][32];        // [br][e][m*4+d]
    float qvec[32];
    float attn[4][16];
    float ao[32];
};

} // namespace

__global__ __launch_bounds__(512, 1)
void eqattn_kernel(
    const float* __restrict__ bk1, const float* __restrict__ bk2,
    const float* __restrict__ bv1, const float* __restrict__ bv2,
    const float* __restrict__ efeat, const float* __restrict__ fin,
    const float* __restrict__ q_w,  const float* __restrict__ q_b,
    const float* __restrict__ k_w1, const float* __restrict__ k_b1,
    const float* __restrict__ k_w2, const float* __restrict__ k_b2,
    const float* __restrict__ v_w1, const float* __restrict__ v_b1,
    const float* __restrict__ v_w2, const float* __restrict__ v_b2,
    const float* __restrict__ o_w,  const float* __restrict__ o_b,
    const int*   __restrict__ nidx32,
    float* __restrict__ out)
{
    extern __shared__ unsigned char smem_raw[];
    SmemT& S = *reinterpret_cast<SmemT*>(smem_raw);
    const int tid = threadIdx.x;

    // int64 vs int32 neighbor_idx sniff, per-thread (no smem round trip):
    // int64 little-endian high words of small indices are 0.
    const bool is64 = (nidx32[1] == 0 && nidx32[3] == 0 &&
                       nidx32[5] == 0 && nidx32[7] == 0);
    const long long* nidx64 = reinterpret_cast<const long long*>(nidx32);

    // ---------------- prologue: stage all weights into smem ----------------
    // w2 repack: value (c, p) with p = i*16 + jh*8 + jq*2 + r.
    // Define lane_r = (i&7)*2 + jh (0..15). Stored at
    //   pos = (i>>3)*128 + jq*32 + lane_r*2 + r
    // so a 16-lane group's float2 reads per (c, jq) are 128B contiguous.
    for (int t = tid; t < 2 * HIDN * FLAT; t += 512) {
        int br  = t >> 14;
        int rem = t & 16383;           // c*256 + p
        int p   = rem & 255;
        const float* g = br ? v_w2 : k_w2;
        float val = g[rem];
        int i  = p >> 4;
        int jh = (p >> 3) & 1;
        int jq = (p >> 1) & 3;
        int r  = p & 1;
        int pos = ((i >> 3) << 7) + (jq << 5) + ((((i & 7) << 1) | jh) << 1) + r;
        S.w2s[br][(rem & ~255) + pos] = val;
    }
    for (int t = tid; t < 2 * EDIM * HIDN; t += 512) {
        int br = t >> 11;
        int rem = t & 2047;
        S.w1s[br][rem] = (br ? v_w1 : k_w1)[rem];
    }
    {
        int br = tid >> 8, p = tid & 255;
        S.b2s[br][p] = (br ? v_b2 : k_b2)[p];
    }
    if (tid < 128) {
        int br = tid >> 6;
        S.b1s[br][tid & 63] = (br ? v_b1 : k_b1)[tid & 63];
        S.qw[tid] = q_w[tid];
        S.ow[tid] = o_w[tid];
    }
    if (tid < 8) { S.qb[tid] = q_b[tid]; S.ob[tid] = o_b[tid]; }

    // prefetch thread roles (fixed over the loop)
    const int pe   = tid >> 5, pi = tid & 31;       // ef / fsrc element
    const int parr = tid >> 7;                      // which basis array
    const int peb  = (tid >> 3) & 15, px = tid & 7; // basis element

    // ------------- prologue: load node n0's inputs into buffer 0 -----------
    {
        const int n0 = blockIdx.x;   // < 152 << NODES, always valid
        long long ib = (long long)n0 * NBR + pe;
        int iv = is64 ? (int)nidx64[ib] : nidx32[ib];
        S.ef[0][pe][pi]   = efeat[(long long)n0 * (NBR * EDIM) + tid];
        S.fsrc[0][pe][pi] = fin[iv * (MULT * DIMV) + pi];
        const float* psrc = (parr == 0) ? bk1 : (parr == 1) ? bk2
                          : (parr == 2) ? bv1 : bv2;
        float bv = psrc[(long long)n0 * (NBR * 8) + peb * 8 + px];
        if (parr == 0)      S.bas1[0][0][peb][px] = bv;
        else if (parr == 1) S.bas2[0][0][peb][px] = bv;
        else if (parr == 2) S.bas1[0][1][peb][px] = bv;
        else                S.bas2[0][1][peb][px] = bv;
        if (tid < 32) S.fnode[0][tid] = fin[n0 * (MULT * DIMV) + tid];
    }
    __syncthreads();

    // layer2 thread geometry (constant over node loop)
    const int warp  = tid >> 5;
    const int lane  = tid & 31;
    const int brw   = warp >> 3;         // branch for layer2 (0=k,1=v)
    const int wb    = warp & 7;
    const int eg2   = wb >> 1;           // edges eg2 + {0,4,8,12}
    const int ihalf = wb & 1;
    const int chalf = lane >> 4;         // 0/1: which half of c in [0,64)
    const int low4  = lane & 15;         // == (irow&7)*2 + jh  (matches repack)
    const int jh    = low4 & 1;
    const int irow  = (ihalf << 3) + (low4 >> 1);   // i in 0..15

    // ---------------------------- node loop --------------------------------
    int pb = 0;
    for (int n = blockIdx.x; n < NODES; n += gridDim.x, pb ^= 1) {

        // ---- issue next node's global loads (consumed at end of iteration)
        const int n2 = n + gridDim.x;
        const bool pf = (n2 < NODES);
        float pf_ef = 0.0f, pf_fs = 0.0f, pf_bas = 0.0f, pf_fn = 0.0f;
        if (pf) {
            long long ib = (long long)n2 * NBR + pe;
            int iv = is64 ? (int)nidx64[ib] : nidx32[ib];
            pf_ef = efeat[(long long)n2 * (NBR * EDIM) + tid];
            pf_fs = fin[iv * (MULT * DIMV) + pi];
            const float* psrc = (parr == 0) ? bk1 : (parr == 1) ? bk2
                              : (parr == 2) ? bv1 : bv2;
            pf_bas = psrc[(long long)n2 * (NBR * 8) + peb * 8 + px];
            if (tid < 32) pf_fn = fin[n2 * (MULT * DIMV) + tid];
        }

        // phase 2: layer1 (h = gelu(ef@w1+b1)), tmp (f_src x bas1), q
        {
            const int br  = tid >> 8;
            const int rem = tid & 255;
            const int c   = rem & 63;
            const int eg  = rem >> 6;        // 0..3, edges eg+4k
            float acc0, acc1, acc2, acc3;
            acc0 = acc1 = acc2 = acc3 = S.b1s[br][c];
            #pragma unroll
            for (int i4 = 0; i4 < EDIM; i4 += 4) {
                float wa = S.w1s[br][(i4 + 0) * HIDN + c];
                float wbv = S.w1s[br][(i4 + 1) * HIDN + c];
                float wc = S.w1s[br][(i4 + 2) * HIDN + c];
                float wd = S.w1s[br][(i4 + 3) * HIDN + c];
                float4 e0 = *reinterpret_cast<const float4*>(&S.ef[pb][eg +  0][i4]);
                float4 e1 = *reinterpret_cast<const float4*>(&S.ef[pb][eg +  4][i4]);
                float4 e2 = *reinterpret_cast<const float4*>(&S.ef[pb][eg +  8][i4]);
                float4 e3 = *reinterpret_cast<const float4*>(&S.ef[pb][eg + 12][i4]);
                acc0 = fmaf(e0.x, wa, acc0); acc0 = fmaf(e0.y, wbv, acc0);
                acc0 = fmaf(e0.z, wc, acc0); acc0 = fmaf(e0.w, wd, acc0);
                acc1 = fmaf(e1.x, wa, acc1); acc1 = fmaf(e1.y, wbv, acc1);
                acc1 = fmaf(e1.z, wc, acc1); acc1 = fmaf(e1.w, wd, acc1);
                acc2 = fmaf(e2.x, wa, acc2); acc2 = fmaf(e2.y, wbv, acc2);
                acc2 = fmaf(e2.z, wc, acc2); acc2 = fmaf(e2.w, wd, acc2);
                acc3 = fmaf(e3.x, wa, acc3); acc3 = fmaf(e3.y, wbv, acc3);
                acc3 = fmaf(e3.z, wc, acc3); acc3 = fmaf(e3.w, wd, acc3);
            }
            // exact gelu: x * Phi(x)
            S.hbuf[br][eg +  0][c] = acc0 * normcdff(acc0);
            S.hbuf[br][eg +  4][c] = acc1 * normcdff(acc1);
            S.hbuf[br][eg +  8][c] = acc2 * normcdff(acc2);
            S.hbuf[br][eg + 12][c] = acc3 * normcdff(acc3);
        }
        {
            const int br = tid >> 8;
            const int rem = tid & 255;
            const int e = rem >> 4;
            const int j = rem & 15;          // m*2 + l
            const int m = j >> 1, l = j & 1;
            const float* fr = S.fsrc[pb][e];
            const float* b  = S.bas1[pb][br][e];
            float t = fr[m * 4 + 0] * b[0 * 2 + l];
            t = fmaf(fr[m * 4 + 1], b[1 * 2 + l], t);
            t = fmaf(fr[m * 4 + 2], b[2 * 2 + l], t);
            t = fmaf(fr[m * 4 + 3], b[3 * 2 + l], t);
            S.tmpb[br][e][j] = t;
        }
        if (tid < 32) {
            const int m = tid >> 2, d = tid & 3;
            const int l = (d == 0) ? 0 : 1;
            float a = (d == 0) ? S.qb[m] : 0.0f;
            #pragma unroll
            for (int mp = 0; mp < MULT; mp++)
                a = fmaf(S.qw[(l * MULT + m) * MULT + mp], S.fnode[pb][mp * 4 + d], a);
            S.qvec[tid] = a;
        }
        __syncthreads();

        // phase 3: layer2 — rw = h@w2 + b2 (c-reduction split across half-warps),
        // then t2 = rw@tmp with shfl folds over (chalf, jh).
        {
            float rw[4][8];
            {
                const int p0 = (irow << 4) + (jh << 3);
                #pragma unroll
                for (int j = 0; j < 8; j++) {
                    // bias seeded only in the chalf==0 partial sum
                    float bb = (chalf == 0) ? S.b2s[brw][p0 + j] : 0.0f;
                    rw[0][j] = bb; rw[1][j] = bb; rw[2][j] = bb; rw[3][j] = bb;
                }
            }
            const float2* w2base =
                reinterpret_cast<const float2*>(&S.w2s[brw][(ihalf << 7) + (low4 << 1)]);
            const float* h0p = S.hbuf[brw][eg2 +  0];
            const float* h1p = S.hbuf[brw][eg2 +  4];
            const float* h2p = S.hbuf[brw][eg2 +  8];
            const float* h3p = S.hbuf[brw][eg2 + 12];
            const int c0 = chalf << 5;
            #pragma unroll 4
            for (int cc = 0; cc < 32; cc++) {
                const int c = c0 + cc;
                float hv0 = h0p[c], hv1 = h1p[c], hv2 = h2p[c], hv3 = h3p[c];
                const float2* wc = w2base + c * 128;   // +c*256 floats
                #pragma unroll
                for (int jq = 0; jq < 4; jq++) {
                    float2 w = wc[jq * 16];            // +jq*32 floats
                    rw[0][2 * jq]     = fmaf(hv0, w.x, rw[0][2 * jq]);
                    rw[0][2 * jq + 1] = fmaf(hv0, w.y, rw[0][2 * jq + 1]);
                    rw[1][2 * jq]     = fmaf(hv1, w.x, rw[1][2 * jq]);
                    rw[1][2 * jq + 1] = fmaf(hv1, w.y, rw[1][2 * jq + 1]);
                    rw[2][2 * jq]     = fmaf(hv2, w.x, rw[2][2 * jq]);
                    rw[2][2 * jq + 1] = fmaf(hv2, w.y, rw[2][2 * jq + 1]);
                    rw[3][2 * jq]     = fmaf(hv3, w.x, rw[3][2 * jq]);
                    rw[3][2 * jq + 1] = fmaf(hv3, w.y, rw[3][2 * jq + 1]);
                }
            }
            #pragma unroll
            for (int k = 0; k < 4; k++) {
                const int e = eg2 + 4 * k;
                const float* tp = &S.tmpb[brw][e][jh << 3];
                float acc = 0.0f;
                #pragma unroll
                for (int j = 0; j < 8; j++) acc = fmaf(rw[k][j], tp[j], acc);
                acc += __shfl_xor_sync(0xffffffffu, acc, 16);  // fold c-halves
                acc += __shfl_xor_sync(0xffffffffu, acc, 1);   // fold j-halves
                if ((lane & 17) == 0) S.t2b[brw][e][irow] = acc;
            }
        }
        __syncthreads();

        // phase 4: k/v = t2 x bas2   (1024 items, 2/thread)
        #pragma unroll
        for (int rep = 0; rep < 2; rep++) {
            int it = tid + rep * 512;
            int br = it >> 9;
            int rem = it & 511;
            int e = rem >> 5;
            int p = rem & 31;                // o*4 + d
            int o = p >> 2, d = p & 3;
            float v = S.t2b[br][e][o * 2 + 0] * S.bas2[pb][br][e][0 * 4 + d];
            v = fmaf(S.t2b[br][e][o * 2 + 1], S.bas2[pb][br][e][1 * 4 + d], v);
            S.kvb[br][e][p] = v;
        }
        __syncthreads();

        // phase 5: logits + softmax (64 threads = warps 0,1; 16-lane groups)
        if (tid < 64) {
            const int h = tid >> 4, kk = tid & 15;
            float acc = 0.0f;
            #pragma unroll
            for (int dd = 0; dd < 8; dd++)
                acc = fmaf(S.qvec[h * 8 + dd], S.kvb[0][kk][h * 8 + dd], acc);
            acc *= ATT_SCALE;
            float mx = acc;
            #pragma unroll
            for (int o = 8; o >= 1; o >>= 1)
                mx = fmaxf(mx, __shfl_xor_sync(0xffffffffu, mx, o));
            float ex = expf(acc - mx);
            float sm = ex;
            #pragma unroll
            for (int o = 8; o >= 1; o >>= 1)
                sm += __shfl_xor_sync(0xffffffffu, sm, o);
            S.attn[h][kk] = ex / sm;
        }
        __syncthreads();

        // phase 6: attention output (32 threads)
        if (tid < 32) {
            const int h = tid >> 3;
            float acc = 0.0f;
            #pragma unroll
            for (int kk = 0; kk < NBR; kk++)
                acc = fmaf(S.attn[h][kk], S.kvb[1][kk][tid], acc);
            S.ao[tid] = acc;
        }
        __syncthreads();

        // phase 7: final eq_linear -> global
        if (tid < 32) {
            const int m = tid >> 2, d = tid & 3;
            const int l = (d == 0) ? 0 : 1;
            float a = (d == 0) ? S.ob[m] : 0.0f;
            #pragma unroll
            for (int mp = 0; mp < MULT; mp++)
                a = fmaf(S.ow[(l * MULT + m) * MULT + mp], S.ao[mp * 4 + d], a);
            out[(long long)n * 32 + tid] = a;
        }

        // ---- commit next node's inputs into the other buffer, then publish
        if (pf) {
            const int nb = pb ^ 1;
            S.ef[nb][pe][pi]   = pf_ef;
            S.fsrc[nb][pe][pi] = pf_fs;
            if (parr == 0)      S.bas1[nb][0][peb][px] = pf_bas;
            else if (parr == 1) S.bas2[nb][0][peb][px] = pf_bas;
            else if (parr == 2) S.bas1[nb][1][peb][px] = pf_bas;
            else                S.bas2[nb][1][peb][px] = pf_bas;
            if (tid < 32) S.fnode[nb][tid] = pf_fn;
        }
        __syncthreads();
    }
}

extern "C" void kernel_launch(void* const* d_in, const int* in_sizes, int n_in,
                              void* d_out, int out_size) {
    const float* bk1  = (const float*)d_in[0];
    const float* bk2  = (const float*)d_in[1];
    const float* bv1  = (const float*)d_in[2];
    const float* bv2  = (const float*)d_in[3];
    const float* ef   = (const float*)d_in[4];
    const float* fin  = (const float*)d_in[5];
    const float* q_w  = (const float*)d_in[6];
    const float* q_b  = (const float*)d_in[7];
    const float* k_w1 = (const float*)d_in[8];
    const float* k_b1 = (const float*)d_in[9];
    const float* k_w2 = (const float*)d_in[10];
    const float* k_b2 = (const float*)d_in[11];
    const float* v_w1 = (const float*)d_in[12];
    const float* v_b1 = (const float*)d_in[13];
    const float* v_w2 = (const float*)d_in[14];
    const float* v_b2 = (const float*)d_in[15];
    const float* o_w  = (const float*)d_in[16];
    const float* o_b  = (const float*)d_in[17];
    const int*   nidx = (const int*)d_in[18];
    float* out = (float*)d_out;

    int sms = 148;
    cudaDeviceGetAttribute(&sms, cudaDevAttrMultiProcessorCount, 0);
    if (sms <= 0) sms = 148;

    const int smem = (int)sizeof(SmemT);
    cudaFuncSetAttribute(eqattn_kernel,
                         cudaFuncAttributeMaxDynamicSharedMemorySize, smem);

    eqattn_kernel<<<sms, 512, smem>>>(
        bk1, bk2, bv1, bv2, ef, fin,
        q_w, q_b, k_w1, k_b1, k_w2, k_b2,
        v_w1, v_b1, v_w2, v_b2, o_w, o_b,
        nidx, out);
}